// round 1
// baseline (speedup 1.0000x reference)
#include <cuda_runtime.h>
#include <math.h>

// GAT_73521250173566
// out[i] = sum_j softmax_j(leaky_relu(a_dst[i]+a_src[j])) * rowmean(h)[j] + mean(bias)
// with h = A @ W. We never form h: compute A @ (W @ [att_src | att_dst | ones])
// in one streaming pass over W (262MB) and x (64.5MB). Memory-bound by design.

#define NC    63        // nodes (EEG channels)
#define DD    250       // time samples
#define KTOT  256000    // 1024 * 1 * 250
#define NOUT  256
#define KC    256       // K-chunk per block
#define NBLK  1000      // KTOT / KC
#define SLOPE 0.2f

// Transposed partials: g_part[(c*3+j)*NBLK + b]. Written fully every launch.
__device__ float g_part[NC * 3 * NBLK];

__global__ void __launch_bounds__(256, 4) proj_kernel(
    const float* __restrict__ x,        // (1024,1,63,250): x[a*15750 + c*250 + d]
    const float* __restrict__ W,        // (256000,256) row-major
    const float* __restrict__ att_src,  // (256,)
    const float* __restrict__ att_dst)  // (256,)
{
    __shared__ float4 vsh[KC];          // per-k (v_src, v_dst, v_sum, pad)
    const int b    = blockIdx.x;
    const int k0   = b * KC;
    const int tid  = threadIdx.x;
    const int wi   = tid >> 5;
    const int lane = tid & 31;

    // Preload attention vectors into registers.
    // Lane t owns n = 4t..4t+3 and n = 128+4t..128+4t+3.
    float as[8], ad[8];
    {
        float4 s0 = reinterpret_cast<const float4*>(att_src)[lane];
        float4 s1 = reinterpret_cast<const float4*>(att_src)[32 + lane];
        float4 t0 = reinterpret_cast<const float4*>(att_dst)[lane];
        float4 t1 = reinterpret_cast<const float4*>(att_dst)[32 + lane];
        as[0]=s0.x; as[1]=s0.y; as[2]=s0.z; as[3]=s0.w;
        as[4]=s1.x; as[5]=s1.y; as[6]=s1.z; as[7]=s1.w;
        ad[0]=t0.x; ad[1]=t0.y; ad[2]=t0.z; ad[3]=t0.w;
        ad[4]=t1.x; ad[5]=t1.y; ad[6]=t1.z; ad[7]=t1.w;
    }

    // ---- Phase A: v[kk] = (W[k]·att_src, W[k]·att_dst, sum(W[k])) ----
    // Warp wi handles kk in [32*wi, 32*wi+32). Fully coalesced W reads.
    #pragma unroll 4
    for (int kk = wi * 32; kk < wi * 32 + 32; kk++) {
        const float4* Wr = reinterpret_cast<const float4*>(W + (size_t)(k0 + kk) * NOUT);
        float4 w0 = Wr[lane];
        float4 w1 = Wr[32 + lane];
        float wv[8] = {w0.x, w0.y, w0.z, w0.w, w1.x, w1.y, w1.z, w1.w};
        float v0 = 0.f, v1 = 0.f, v2 = 0.f;
        #pragma unroll
        for (int j = 0; j < 8; j++) {
            v0 = fmaf(wv[j], as[j], v0);
            v1 = fmaf(wv[j], ad[j], v1);
            v2 += wv[j];
        }
        #pragma unroll
        for (int off = 16; off > 0; off >>= 1) {
            v0 += __shfl_xor_sync(0xffffffffu, v0, off);
            v1 += __shfl_xor_sync(0xffffffffu, v1, off);
            v2 += __shfl_xor_sync(0xffffffffu, v2, off);
        }
        if (lane == 0) vsh[kk] = make_float4(v0, v1, v2, 0.0f);
    }
    __syncthreads();

    // ---- Phase B: acc[c] += x[c, k] * v[k] over the chunk ----
    // Warp wi owns rows c = wi, wi+8, ... (<= 8 rows). Lane = kk offset:
    // consecutive lanes -> consecutive d -> coalesced x reads.
    float acc[8][3];
    #pragma unroll
    for (int r = 0; r < 8; r++) acc[r][0] = acc[r][1] = acc[r][2] = 0.f;

    #pragma unroll
    for (int it = 0; it < KC / 32; it++) {
        const int kk = it * 32 + lane;
        const int k  = k0 + kk;
        const int a  = k / DD;            // magic-mul division by 250
        const int d  = k - a * DD;
        const float* xp = x + (size_t)a * (NC * DD) + d;
        const float4 v  = vsh[kk];
        #pragma unroll
        for (int r = 0; r < 8; r++) {
            const int c = wi + (r << 3);
            if (c < NC) {
                float xv = xp[c * DD];
                acc[r][0] = fmaf(xv, v.x, acc[r][0]);
                acc[r][1] = fmaf(xv, v.y, acc[r][1]);
                acc[r][2] = fmaf(xv, v.z, acc[r][2]);
            }
        }
    }

    // ---- Deterministic block reduce -> transposed global partials ----
    #pragma unroll
    for (int r = 0; r < 8; r++) {
        const int c = wi + (r << 3);
        if (c < NC) {
            float s0 = acc[r][0], s1 = acc[r][1], s2 = acc[r][2];
            #pragma unroll
            for (int off = 16; off > 0; off >>= 1) {
                s0 += __shfl_xor_sync(0xffffffffu, s0, off);
                s1 += __shfl_xor_sync(0xffffffffu, s1, off);
                s2 += __shfl_xor_sync(0xffffffffu, s2, off);
            }
            if (lane == 0) {
                g_part[(c * 3 + 0) * NBLK + b] = s0;
                g_part[(c * 3 + 1) * NBLK + b] = s1;
                g_part[(c * 3 + 2) * NBLK + b] = s2;
            }
        }
    }
}

__global__ void __launch_bounds__(1024) finish_kernel(
    const float* __restrict__ bias, float* __restrict__ out)
{
    __shared__ float red[5][NC * 3];
    __shared__ float accv[NC * 3];
    __shared__ float sb[256];
    const int tid = threadIdx.x;
    const int col = tid % (NC * 3);
    const int seg = tid / (NC * 3);

    // Stage 1: 5 segments x 189 columns; each thread sums 200 contiguous floats.
    if (seg < 5) {
        const float4* gp = reinterpret_cast<const float4*>(g_part + col * NBLK + seg * 200);
        float s = 0.f;
        #pragma unroll 5
        for (int q = 0; q < 50; q++) {
            float4 v = gp[q];
            s += (v.x + v.y) + (v.z + v.w);
        }
        red[seg][col] = s;
    }
    if (tid < 256) sb[tid] = bias[tid];
    __syncthreads();

    if (tid < NC * 3)
        accv[tid] = ((red[0][tid] + red[1][tid]) + (red[2][tid] + red[3][tid])) + red[4][tid];

    // Deterministic tree reduce of bias (uniform control flow around syncs).
    #pragma unroll
    for (int st = 128; st > 0; st >>= 1) {
        __syncthreads();
        if (tid < st) sb[tid] += sb[tid + st];
    }
    __syncthreads();
    const float bias_mean = sb[0] * (1.0f / NOUT);

    // Stage 2: 63x63 leaky_relu + softmax + weighted sum of rowmean(h).
    if (tid < NC) {
        const float adi = accv[tid * 3 + 1];
        float m = -1e30f;
        for (int j = 0; j < NC; j++) {
            float z = adi + accv[j * 3 + 0];
            float e = z > 0.f ? z : SLOPE * z;
            m = fmaxf(m, e);
        }
        float ssum = 0.f, osum = 0.f;
        for (int j = 0; j < NC; j++) {
            float z = adi + accv[j * 3 + 0];
            float e = z > 0.f ? z : SLOPE * z;
            float wg = expf(e - m);
            ssum += wg;
            osum = fmaf(wg, accv[j * 3 + 2], osum);
        }
        out[tid] = osum * (1.0f / NOUT) / ssum + bias_mean;
    }
}

extern "C" void kernel_launch(void* const* d_in, const int* in_sizes, int n_in,
                              void* d_out, int out_size) {
    const float* x       = (const float*)d_in[0];
    const float* W       = (const float*)d_in[1];
    const float* att_src = (const float*)d_in[2];
    const float* att_dst = (const float*)d_in[3];
    const float* bias    = (const float*)d_in[4];
    float* out = (float*)d_out;

    proj_kernel<<<NBLK, 256>>>(x, W, att_src, att_dst);
    finish_kernel<<<1, 1024>>>(bias, out);
}

// round 2
// speedup vs baseline: 1.0341x; 1.0341x over previous
#include <cuda_runtime.h>
#include <math.h>

// GAT_73521250173566 — single fused kernel.
// out[i] = sum_j softmax_j(leaky_relu(a_dst[i]+a_src[j])) * rowmean(h)[j] + mean(bias)
// with h = A @ W. Never form h: compute A @ (W @ [att_src | att_dst | ones]) in one
// streaming pass over W (262MB) + x (64.5MB). Finish (reduce + 63x63 softmax) is
// fused via the last-block pattern to kill the 22.8us second-kernel tail.

#define NC    63        // nodes (EEG channels)
#define DD    250       // time samples
#define KTOT  256000    // 1024 * 1 * 250
#define NOUT  256
#define KC    512       // K-chunk per block
#define NBLK  500       // KTOT / KC
#define SLOPE 0.2f

// Transposed partials: g_part[(c*3+j)*NBLK + b]. Fully rewritten every launch.
__device__ __align__(16) float g_part[NC * 3 * NBLK];
__device__ int g_cnt = 0;   // reset to 0 by the last block each launch

__global__ void __launch_bounds__(256, 4) gat_fused_kernel(
    const float* __restrict__ x,        // (1024,1,63,250): x[a*15750 + c*250 + d]
    const float* __restrict__ W,        // (256000,256) row-major
    const float* __restrict__ att_src,  // (256,)
    const float* __restrict__ att_dst,  // (256,)
    const float* __restrict__ bias,     // (256,)
    float* __restrict__ out)            // (63,)
{
    __shared__ float4 vsh[KC];          // per-k (v_src, v_dst, v_sum, pad): 8KB
    __shared__ float accv[NC * 3];
    __shared__ float sb[256];
    __shared__ int   is_last;

    const int b    = blockIdx.x;
    const int k0   = b * KC;
    const int tid  = threadIdx.x;
    const int wi   = tid >> 5;
    const int lane = tid & 31;

    // Attention vectors in registers. Lane t owns n = 4t..4t+3 and 128+4t..128+4t+3.
    float as[8], ad[8];
    {
        float4 s0 = reinterpret_cast<const float4*>(att_src)[lane];
        float4 s1 = reinterpret_cast<const float4*>(att_src)[32 + lane];
        float4 t0 = reinterpret_cast<const float4*>(att_dst)[lane];
        float4 t1 = reinterpret_cast<const float4*>(att_dst)[32 + lane];
        as[0]=s0.x; as[1]=s0.y; as[2]=s0.z; as[3]=s0.w;
        as[4]=s1.x; as[5]=s1.y; as[6]=s1.z; as[7]=s1.w;
        ad[0]=t0.x; ad[1]=t0.y; ad[2]=t0.z; ad[3]=t0.w;
        ad[4]=t1.x; ad[5]=t1.y; ad[6]=t1.z; ad[7]=t1.w;
    }

    // ---- Phase A: v[kk] = (W[k]·att_src, W[k]·att_dst, sum(W[k])) ----
    // Warp wi handles kk in [64*wi, 64*wi+64). Fully coalesced 128b W reads.
    #pragma unroll 4
    for (int kk = wi * 64; kk < wi * 64 + 64; kk++) {
        const float4* Wr = reinterpret_cast<const float4*>(W + (size_t)(k0 + kk) * NOUT);
        float4 w0 = Wr[lane];
        float4 w1 = Wr[32 + lane];
        float wv[8] = {w0.x, w0.y, w0.z, w0.w, w1.x, w1.y, w1.z, w1.w};
        float v0 = 0.f, v1 = 0.f, v2 = 0.f;
        #pragma unroll
        for (int j = 0; j < 8; j++) {
            v0 = fmaf(wv[j], as[j], v0);
            v1 = fmaf(wv[j], ad[j], v1);
            v2 += wv[j];
        }
        #pragma unroll
        for (int off = 16; off > 0; off >>= 1) {
            v0 += __shfl_xor_sync(0xffffffffu, v0, off);
            v1 += __shfl_xor_sync(0xffffffffu, v1, off);
            v2 += __shfl_xor_sync(0xffffffffu, v2, off);
        }
        if (lane == 0) vsh[kk] = make_float4(v0, v1, v2, 0.0f);
    }
    __syncthreads();

    // ---- Phase B: acc[c] += x[c, k] * v[k] over the chunk ----
    // Warp wi owns rows c = wi, wi+8, ... (8 rows, c<63). Lanes stride k:
    // consecutive lanes -> consecutive d -> coalesced x reads.
    float acc[8][3];
    #pragma unroll
    for (int r = 0; r < 8; r++) acc[r][0] = acc[r][1] = acc[r][2] = 0.f;

    #pragma unroll
    for (int it = 0; it < KC / 32; it++) {
        const int kk = it * 32 + lane;
        const int k  = k0 + kk;
        const int a  = k / DD;
        const int d  = k - a * DD;
        const float* xp = x + (size_t)a * (NC * DD) + d;
        const float4 v  = vsh[kk];
        #pragma unroll
        for (int r = 0; r < 8; r++) {
            const int c = wi + (r << 3);
            if (c < NC) {
                float xv = xp[c * DD];
                acc[r][0] = fmaf(xv, v.x, acc[r][0]);
                acc[r][1] = fmaf(xv, v.y, acc[r][1]);
                acc[r][2] = fmaf(xv, v.z, acc[r][2]);
            }
        }
    }

    // ---- Deterministic block reduce -> transposed global partials ----
    #pragma unroll
    for (int r = 0; r < 8; r++) {
        const int c = wi + (r << 3);
        if (c < NC) {
            float s0 = acc[r][0], s1 = acc[r][1], s2 = acc[r][2];
            #pragma unroll
            for (int off = 16; off > 0; off >>= 1) {
                s0 += __shfl_xor_sync(0xffffffffu, s0, off);
                s1 += __shfl_xor_sync(0xffffffffu, s1, off);
                s2 += __shfl_xor_sync(0xffffffffu, s2, off);
            }
            if (lane == 0) {
                g_part[(c * 3 + 0) * NBLK + b] = s0;
                g_part[(c * 3 + 1) * NBLK + b] = s1;
                g_part[(c * 3 + 2) * NBLK + b] = s2;
            }
        }
    }

    // ---- Last-block election (threadFenceReduction pattern) ----
    __threadfence();
    __syncthreads();
    if (tid == 0) {
        int v = atomicAdd(&g_cnt, 1);
        is_last = (v == NBLK - 1);
    }
    __syncthreads();
    if (!is_last) return;

    // ==== FINISH (runs in exactly one block, all partials visible) ====

    // Stage 1: thread t < 189 sums its whole column (500 floats = 125 float4,
    // L2-resident, independent loads -> high MLP).
    if (tid < NC * 3) {
        const float4* gp = reinterpret_cast<const float4*>(g_part + tid * NBLK);
        float s = 0.f;
        #pragma unroll 5
        for (int q = 0; q < NBLK / 4; q++) {
            float4 v = gp[q];
            s += (v.x + v.y) + (v.z + v.w);
        }
        accv[tid] = s;
    }
    sb[tid] = bias[tid];              // 256 threads, 256 bias elems
    __syncthreads();

    // Deterministic tree reduce of bias (uniform control flow around syncs).
    #pragma unroll
    for (int st = 128; st > 0; st >>= 1) {
        if (tid < st) sb[tid] += sb[tid + st];
        __syncthreads();
    }
    const float bias_mean = sb[0] * (1.0f / NOUT);

    // Stage 2: 63x63 leaky_relu + softmax + weighted sum of rowmean(h).
    if (tid < NC) {
        const float adi = accv[tid * 3 + 1];
        float m = -1e30f;
        #pragma unroll 7
        for (int j = 0; j < NC; j++) {
            float z = adi + accv[j * 3 + 0];
            float e = z > 0.f ? z : SLOPE * z;
            m = fmaxf(m, e);
        }
        float ssum = 0.f, osum = 0.f;
        #pragma unroll 7
        for (int j = 0; j < NC; j++) {
            float z = adi + accv[j * 3 + 0];
            float e = z > 0.f ? z : SLOPE * z;
            float wg = expf(e - m);
            ssum += wg;
            osum = fmaf(wg, accv[j * 3 + 2], osum);
        }
        out[tid] = osum * (1.0f / NOUT) / ssum + bias_mean;
    }

    if (tid == 0) g_cnt = 0;          // re-arm for next graph replay
}

extern "C" void kernel_launch(void* const* d_in, const int* in_sizes, int n_in,
                              void* d_out, int out_size) {
    const float* x       = (const float*)d_in[0];
    const float* W       = (const float*)d_in[1];
    const float* att_src = (const float*)d_in[2];
    const float* att_dst = (const float*)d_in[3];
    const float* bias    = (const float*)d_in[4];
    float* out = (float*)d_out;

    gat_fused_kernel<<<NBLK, 256>>>(x, W, att_src, att_dst, bias, out);
}